// round 8
// baseline (speedup 1.0000x reference)
#include <cuda_runtime.h>
#include <math.h>
#include <stdint.h>

#define BB 64
#define TT 512
#define DD 1024
#define HH 1024
#define HG 4096          // 4 gates * H

typedef unsigned long long ull;

// packed f32x2 fma: d = a*b + d  (lane-wise fp32, bit-exact vs scalar FFMA)
__device__ __forceinline__ void ffma2(ull& d, ull a, ull b) {
    asm("fma.rn.f32x2 %0, %1, %2, %0;" : "+l"(d) : "l"(a), "l"(b));
}
__device__ __forceinline__ ull pack2(float lo, float hi) {
    ull r;
    asm("mov.b64 %0, {%1, %2};" : "=l"(r) : "f"(lo), "f"(hi));
    return r;
}
__device__ __forceinline__ void unpack2(float& lo, float& hi, ull v) {
    asm("mov.b64 {%0, %1}, %2;" : "=f"(lo), "=f"(hi) : "l"(v));
}

// ---------------- device scratch (no cudaMalloc allowed) ----------------
__device__ float g_Wx[DD * HG];                 // 16 MB  [k][gate*H+n] (gate-major)
__device__ float g_Whp[HH * HG];                // 16 MB  [k][packed col] gate-interleaved
__device__ float g_bias[HG];                    // folded b_i* + b_h*
__device__ float g_xact[(size_t)TT * BB * HG];  // 512 MB [t][b][packed col]
__device__ float g_hbuf[2][BB * HH];            // ping-pong hidden state (race-free)
__device__ unsigned g_bar_count = 0;            // grid barrier
__device__ unsigned g_bar_gen = 0;

// packed col for (gate g, hidden n): CTA j=n>>3 owns n, cols [j*32, j*32+32)
// pc = (n>>3)*32 + (n&7)*4 + g  -> the 4 gates {i,f,g,o} of one n are one float4
__device__ __forceinline__ int pcol(int n) { return ((n >> 3) << 5) + ((n & 7) << 2); }

// ---------------- pack: permute weights, fold biases, zero state ----------------
__global__ void pack_kernel(
    const float* __restrict__ Wii, const float* __restrict__ Wif,
    const float* __restrict__ Wig, const float* __restrict__ Wio,
    const float* __restrict__ Whi, const float* __restrict__ Whf,
    const float* __restrict__ Whg, const float* __restrict__ Who,
    const float* __restrict__ bii, const float* __restrict__ bif,
    const float* __restrict__ big, const float* __restrict__ bio,
    const float* __restrict__ bhi, const float* __restrict__ bhf,
    const float* __restrict__ bhg, const float* __restrict__ bho)
{
    int gtid = blockIdx.x * blockDim.x + threadIdx.x;
    int stride = gridDim.x * blockDim.x;

    for (int idx = gtid; idx < DD * HH; idx += stride) {
        int k = idx >> 10;       // / H
        int n = idx & 1023;      // % H
        int base = k * HG + n;
        g_Wx[base + 0 * HH] = Wii[idx];
        g_Wx[base + 1 * HH] = Wif[idx];
        g_Wx[base + 2 * HH] = Wig[idx];
        g_Wx[base + 3 * HH] = Wio[idx];
        int pb = k * HG + pcol(n);
        g_Whp[pb + 0] = Whi[idx];
        g_Whp[pb + 1] = Whf[idx];
        g_Whp[pb + 2] = Whg[idx];
        g_Whp[pb + 3] = Who[idx];
    }
    for (int idx = gtid; idx < BB * HH; idx += stride) {
        g_hbuf[0][idx] = 0.0f;
        g_hbuf[1][idx] = 0.0f;
    }
    for (int idx = gtid; idx < HH; idx += stride) {
        g_bias[0 * HH + idx] = bii[idx] + bhi[idx];
        g_bias[1 * HH + idx] = bif[idx] + bhf[idx];
        g_bias[2 * HH + idx] = big[idx] + bhg[idx];
        g_bias[3 * HH + idx] = bio[idx] + bho[idx];
    }
}

// ---------------- phase 1: g_xact = x @ Wx + bias (packed layout) ----------------
// A tile stored duplicated {a,a} pairs; B tile stored column-pair interleaved so
// all hot-loop LDS are conflict-free LDS.64 and the loop has zero pack MOVs.
#define BM 128
#define BN 128
#define BK 16
#define XS2_ST (2 * BM + 4)    // 260, xs2 row stride in floats

__global__ __launch_bounds__(256, 2)
void gemm_x_kernel(const float* __restrict__ X)
{
    __shared__ float xs2[BK][XS2_ST];   // [k][2m]  dup pairs {a,a}
    __shared__ float ws2[BK][BN];       // [k][pos] pos = j*32 + tx*2 + e  (n = tx*8+2j+e)

    const int m0 = blockIdx.y * BM;
    const int n0 = blockIdx.x * BN;
    const int tid = threadIdx.x;
    const int ty = tid >> 4;       // 0..15
    const int tx = tid & 15;       // 0..15

    ull acc2[8][4];                // 8 rows x 4 col-pairs, packed f32x2
    #pragma unroll
    for (int i = 0; i < 8; i++)
        #pragma unroll
        for (int j = 0; j < 4; j++) acc2[i][j] = 0ULL;

    for (int k0 = 0; k0 < DD; k0 += BK) {
        // X tile: 128 rows x 16 k, store transposed + duplicated
        #pragma unroll
        for (int i = 0; i < 2; i++) {
            int idx = tid + i * 256;            // 0..511
            int row = idx >> 2;                 // 0..127
            int v = (idx & 3) * 4;              // 0,4,8,12
            float4 f = *(const float4*)(X + (size_t)(m0 + row) * DD + k0 + v);
            *(ull*)&xs2[v + 0][2 * row] = pack2(f.x, f.x);
            *(ull*)&xs2[v + 1][2 * row] = pack2(f.y, f.y);
            *(ull*)&xs2[v + 2][2 * row] = pack2(f.z, f.z);
            *(ull*)&xs2[v + 3][2 * row] = pack2(f.w, f.w);
        }
        // W tile: 16 k x 128 n, store pair-interleaved: n=tx*8+2j+e -> pos=j*32+tx*2+e
        #pragma unroll
        for (int i = 0; i < 2; i++) {
            int idx = tid + i * 256;            // 0..511
            int row = idx >> 5;                 // 0..15
            int vc = (idx & 31) * 4;            // 0..124 (multiple of 4)
            float4 f = *(const float4*)(g_Wx + (size_t)(k0 + row) * HG + n0 + vc);
            int pb = ((vc & 4) >> 1) * 32 + (vc >> 3) * 2;
            *(ull*)&ws2[row][pb]      = pack2(f.x, f.y);   // cols vc, vc+1
            *(ull*)&ws2[row][pb + 32] = pack2(f.z, f.w);   // cols vc+2, vc+3
        }
        __syncthreads();

        #pragma unroll
        for (int kk = 0; kk < BK; kk++) {
            ull ap[8], bp[4];
            #pragma unroll
            for (int i = 0; i < 8; i++)
                ap[i] = *(const ull*)&xs2[kk][2 * (ty * 8 + i)];      // {a,a}
            #pragma unroll
            for (int j = 0; j < 4; j++)
                bp[j] = *(const ull*)&ws2[kk][j * 32 + tx * 2];       // {w_n, w_n+1}
            #pragma unroll
            for (int i = 0; i < 8; i++)
                #pragma unroll
                for (int j = 0; j < 4; j++)
                    ffma2(acc2[i][j], ap[i], bp[j]);
        }
        __syncthreads();
    }

    // epilogue: add bias, write into packed [t][b][pc] layout
    #pragma unroll
    for (int i = 0; i < 8; i++) {
        int m = m0 + ty * 8 + i;   // m = b*T + t
        int b = m >> 9;            // / 512
        int t = m & 511;
        size_t rowbase = ((size_t)t * BB + b) * HG;
        float accf[8];
        #pragma unroll
        for (int j = 0; j < 4; j++)
            unpack2(accf[2 * j], accf[2 * j + 1], acc2[i][j]);
        #pragma unroll
        for (int j = 0; j < 8; j++) {
            int c = n0 + tx * 8 + j;          // original column (gate-major)
            int g = c >> 10;
            int n = c & 1023;
            g_xact[rowbase + pcol(n) + g] = accf[j] + g_bias[c];
        }
    }
}

// ---------------- software grid barrier (all 128 CTAs co-resident) ----------------
__device__ __forceinline__ void grid_sync_all()
{
    __threadfence();          // flush h stores to GPU scope
    __syncthreads();
    if (threadIdx.x == 0) {
        unsigned gen = atomicAdd(&g_bar_gen, 0u);   // read gen BEFORE arriving
        unsigned arrived = atomicAdd(&g_bar_count, 1u);
        if (arrived == gridDim.x - 1) {
            g_bar_count = 0;
            __threadfence();
            atomicExch(&g_bar_gen, gen + 1u);
        } else {
            while (atomicAdd(&g_bar_gen, 0u) == gen) { __nanosleep(32); }
        }
        __threadfence();
    }
    __syncthreads();
}

// ---------------- persistent recurrence kernel ----------------
// 128 CTAs x 256 threads. CTA j owns n in [8j, 8j+8), all 4 gates, all 64 batches.
// Thread (u = tid&7, brow = tid>>3) owns (b=brow, n=8j+u) and (b=brow+32, n=8j+u).
// c lives in registers for all 512 steps. Hot loop: 1 LDS.128 + 2 LDS.64 + 4 FFMA2.
#define PCTAS 128
#define KCHUNK 128
#define NTILE (HH / KCHUNK)     // 8
#define HS_ST 256               // hs2[b][2k]: dup pairs {h,h}, 64 x 256 floats

__global__ __launch_bounds__(256, 1)
void lstm_persist_kernel(float* __restrict__ out)
{
    extern __shared__ float smem[];
    float* ws_all = smem;                       // [1024][32] = 128 KB (Wh slice)
    float* hs2 = smem + HH * 32;                // [64][256]  =  64 KB (dup'd h tile)

    const int j = blockIdx.x;
    const int tid = threadIdx.x;
    const int u = tid & 7;
    const int brow = tid >> 3;                  // 0..31

    // ---- load this CTA's Wh slice into smem (once) ----
    {
        const float4* src = (const float4*)(g_Whp);
        float4* dst = (float4*)ws_all;
        for (int i = tid; i < HH * 8; i += 256) {
            int k = i >> 3;
            int cc = i & 7;
            dst[k * 8 + cc] = src[(size_t)k * (HG / 4) + j * 8 + cc];
        }
    }
    __syncthreads();

    float creg[2] = {0.0f, 0.0f};
    const int ng = j * 8 + u;                   // global n owned by this thread

    // h-tile loader: 2048 float4 per tile, 8 per thread, fully coalesced.
    // idx = tid + 256r: b = idx>>5 (warp-uniform), c4 = idx&31 (lane) -> contiguous.
    float4 pf[8];

    for (int t = 0; t < TT; t++) {
        const float* hcur = g_hbuf[t & 1];
        float* hnxt = g_hbuf[(t + 1) & 1];

        ull accif0 = 0ULL, accgo0 = 0ULL;       // batch brow:    {i,f} {g,o}
        ull accif1 = 0ULL, accgo1 = 0ULL;       // batch brow+32

        #pragma unroll 1
        for (int tile = 0; tile < NTILE; tile++) {
            __syncthreads();   // previous tile's hs2 readers done
            if (tile == 0) {
                #pragma unroll
                for (int r = 0; r < 8; r++) {
                    int idx = tid + r * 256;
                    pf[r] = __ldcg((const float4*)(hcur + (idx >> 5) * HH + (idx & 31) * 4));
                }
            }
            // store dup'd: hs2[b][2k..2k+7] = {x,x,y,y,z,z,w,w} -> 2 contiguous STS.128
            #pragma unroll
            for (int r = 0; r < 8; r++) {
                int idx = tid + r * 256;
                int b = idx >> 5, c4 = idx & 31;
                float* p = &hs2[b * HS_ST + c4 * 8];
                ((ull*)p)[0] = pack2(pf[r].x, pf[r].x);
                ((ull*)p)[1] = pack2(pf[r].y, pf[r].y);
                ((ull*)p)[2] = pack2(pf[r].z, pf[r].z);
                ((ull*)p)[3] = pack2(pf[r].w, pf[r].w);
            }
            // prefetch next tile (hidden under compute)
            if (tile < NTILE - 1) {
                #pragma unroll
                for (int r = 0; r < 8; r++) {
                    int idx = tid + r * 256;
                    pf[r] = __ldcg((const float4*)(hcur + (idx >> 5) * HH +
                                                   (tile + 1) * KCHUNK + (idx & 31) * 4));
                }
            }
            __syncthreads();   // hs2 ready

            const int kw0 = tile * KCHUNK;
            #pragma unroll 8
            for (int kk = 0; kk < KCHUNK; kk++) {
                // weights: float4 {i,f,g,o} -> two ready f32x2 operands (one LDS.128)
                ulonglong2 wv = *(const ulonglong2*)&ws_all[(kw0 + kk) * 32 + u * 4];
                // activations: pre-duplicated pairs (one LDS.64 each, zero MOVs)
                ull ap0 = *(const ull*)&hs2[brow * HS_ST + 2 * kk];
                ull ap1 = *(const ull*)&hs2[(brow + 32) * HS_ST + 2 * kk];
                ffma2(accif0, ap0, wv.x);
                ffma2(accgo0, ap0, wv.y);
                ffma2(accif1, ap1, wv.x);
                ffma2(accgo1, ap1, wv.y);
            }
        }

        // ---- pointwise: gates -> c,h (c in registers) ----
        #pragma unroll
        for (int e = 0; e < 2; e++) {
            int b = brow + 32 * e;
            float si, sf, sg, so;
            if (e == 0) { unpack2(si, sf, accif0); unpack2(sg, so, accgo0); }
            else        { unpack2(si, sf, accif1); unpack2(sg, so, accgo1); }
            float4 xa = __ldcs((const float4*)(g_xact +
                         ((size_t)t * BB + b) * HG + j * 32 + u * 4));
            float pi = si + xa.x;
            float pff = sf + xa.y;
            float pg = sg + xa.z;
            float po = so + xa.w;

            float it_ = 1.0f / (1.0f + expf(-pi));
            float ft = 1.0f / (1.0f + expf(-pff));
            float gt = tanhf(pg);
            float ot = 1.0f / (1.0f + expf(-po));

            float c = ft * creg[e] + it_ * gt;
            float h = ot * tanhf(c);
            creg[e] = c;

            hnxt[b * HH + ng] = h;
            out[((size_t)b * TT + t) * HH + ng] = h;
        }

        grid_sync_all();   // h(t+1) fully written before any CTA starts step t+1
    }
}

// ---------------- launch ----------------
extern "C" void kernel_launch(void* const* d_in, const int* in_sizes, int n_in,
                              void* d_out, int out_size)
{
    const float* x   = (const float*)d_in[0];
    const float* Wii = (const float*)d_in[1];
    const float* bii = (const float*)d_in[2];
    const float* Whi = (const float*)d_in[3];
    const float* bhi = (const float*)d_in[4];
    const float* Wif = (const float*)d_in[5];
    const float* bif = (const float*)d_in[6];
    const float* Whf = (const float*)d_in[7];
    const float* bhf = (const float*)d_in[8];
    const float* Wig = (const float*)d_in[9];
    const float* big = (const float*)d_in[10];
    const float* Whg = (const float*)d_in[11];
    const float* bhg = (const float*)d_in[12];
    const float* Wio = (const float*)d_in[13];
    const float* bio = (const float*)d_in[14];
    const float* Who = (const float*)d_in[15];
    const float* bho = (const float*)d_in[16];
    float* out = (float*)d_out;

    pack_kernel<<<512, 256>>>(Wii, Wif, Wig, Wio, Whi, Whf, Whg, Who,
                              bii, bif, big, bio, bhi, bhf, bhg, bho);

    // phase 1: (32768 x 4096) = X (32768 x 1024) @ Wx (1024 x 4096)
    gemm_x_kernel<<<dim3(HG / BN, (BB * TT) / BM), 256>>>(x);

    // phase 2: single persistent kernel for all 512 steps
    const int smem_bytes = (HH * 32 + BB * HS_ST) * (int)sizeof(float); // 192 KB
    cudaFuncSetAttribute(lstm_persist_kernel,
                         cudaFuncAttributeMaxDynamicSharedMemorySize, smem_bytes);
    lstm_persist_kernel<<<PCTAS, 256, smem_bytes>>>(out);
}

// round 9
// speedup vs baseline: 1.8761x; 1.8761x over previous
#include <cuda_runtime.h>
#include <math.h>
#include <stdint.h>

#define BB 64
#define TT 512
#define DD 1024
#define HH 1024
#define HG 4096          // 4 gates * H

typedef unsigned long long ull;

// packed f32x2 ops (lane-wise fp32, bit-exact vs scalar)
__device__ __forceinline__ void ffma2(ull& d, ull a, ull b) {
    asm("fma.rn.f32x2 %0, %1, %2, %0;" : "+l"(d) : "l"(a), "l"(b));
}
__device__ __forceinline__ ull fadd2(ull a, ull b) {
    ull r;
    asm("add.rn.f32x2 %0, %1, %2;" : "=l"(r) : "l"(a), "l"(b));
    return r;
}
__device__ __forceinline__ ull pack2(float lo, float hi) {
    ull r;
    asm("mov.b64 %0, {%1, %2};" : "=l"(r) : "f"(lo), "f"(hi));
    return r;
}
__device__ __forceinline__ void unpack2(float& lo, float& hi, ull v) {
    asm("mov.b64 {%0, %1}, %2;" : "=f"(lo), "=f"(hi) : "l"(v));
}

// ---------------- device scratch (no cudaMalloc allowed) ----------------
__device__ float g_Wx[DD * HG];                 // 16 MB  [k][gate*H+n] (gate-major)
__device__ float g_Whp[HH * HG];                // 16 MB  [k][packed col] gate-interleaved
__device__ float g_bias[HG];                    // folded b_i* + b_h*
__device__ float g_xact[(size_t)TT * BB * HG];  // 512 MB [t][b][packed col]
__device__ float g_hbufT[2][HH * BB];           // ping-pong hidden state, TRANSPOSED [n][b]
__device__ unsigned g_bar_count = 0;            // grid barrier
__device__ unsigned g_bar_gen = 0;

// packed col for (gate g, hidden n): CTA j=n>>3 owns n, cols [j*32, j*32+32)
// pc = (n>>3)*32 + (n&7)*4 + g  -> the 4 gates {i,f,g,o} of one n are one float4
__device__ __forceinline__ int pcol(int n) { return ((n >> 3) << 5) + ((n & 7) << 2); }

// ---------------- pack: permute weights, fold biases, zero state ----------------
__global__ void pack_kernel(
    const float* __restrict__ Wii, const float* __restrict__ Wif,
    const float* __restrict__ Wig, const float* __restrict__ Wio,
    const float* __restrict__ Whi, const float* __restrict__ Whf,
    const float* __restrict__ Whg, const float* __restrict__ Who,
    const float* __restrict__ bii, const float* __restrict__ bif,
    const float* __restrict__ big, const float* __restrict__ bio,
    const float* __restrict__ bhi, const float* __restrict__ bhf,
    const float* __restrict__ bhg, const float* __restrict__ bho)
{
    int gtid = blockIdx.x * blockDim.x + threadIdx.x;
    int stride = gridDim.x * blockDim.x;

    for (int idx = gtid; idx < DD * HH; idx += stride) {
        int k = idx >> 10;       // / H
        int n = idx & 1023;      // % H
        int base = k * HG + n;
        g_Wx[base + 0 * HH] = Wii[idx];
        g_Wx[base + 1 * HH] = Wif[idx];
        g_Wx[base + 2 * HH] = Wig[idx];
        g_Wx[base + 3 * HH] = Wio[idx];
        int pb = k * HG + pcol(n);
        g_Whp[pb + 0] = Whi[idx];
        g_Whp[pb + 1] = Whf[idx];
        g_Whp[pb + 2] = Whg[idx];
        g_Whp[pb + 3] = Who[idx];
    }
    for (int idx = gtid; idx < BB * HH; idx += stride) {
        g_hbufT[0][idx] = 0.0f;
        g_hbufT[1][idx] = 0.0f;
    }
    for (int idx = gtid; idx < HH; idx += stride) {
        g_bias[0 * HH + idx] = bii[idx] + bhi[idx];
        g_bias[1 * HH + idx] = bif[idx] + bhf[idx];
        g_bias[2 * HH + idx] = big[idx] + bhg[idx];
        g_bias[3 * HH + idx] = bio[idx] + bho[idx];
    }
}

// ---------------- phase 1: g_xact = x @ Wx + bias (packed layout) ----------------
// (unchanged from round 8 — single-change discipline; recurrence is this round's target)
#define BM 128
#define BN 128
#define BK 16
#define XS2_ST (2 * BM + 4)    // 260

__global__ __launch_bounds__(256, 2)
void gemm_x_kernel(const float* __restrict__ X)
{
    __shared__ float xs2[BK][XS2_ST];   // [k][2m]  dup pairs {a,a}
    __shared__ float ws2[BK][BN];       // [k][pos] pos = j*32 + tx*2 + e

    const int m0 = blockIdx.y * BM;
    const int n0 = blockIdx.x * BN;
    const int tid = threadIdx.x;
    const int ty = tid >> 4;
    const int tx = tid & 15;

    ull acc2[8][4];
    #pragma unroll
    for (int i = 0; i < 8; i++)
        #pragma unroll
        for (int j = 0; j < 4; j++) acc2[i][j] = 0ULL;

    for (int k0 = 0; k0 < DD; k0 += BK) {
        #pragma unroll
        for (int i = 0; i < 2; i++) {
            int idx = tid + i * 256;
            int row = idx >> 2;
            int v = (idx & 3) * 4;
            float4 f = *(const float4*)(X + (size_t)(m0 + row) * DD + k0 + v);
            *(ull*)&xs2[v + 0][2 * row] = pack2(f.x, f.x);
            *(ull*)&xs2[v + 1][2 * row] = pack2(f.y, f.y);
            *(ull*)&xs2[v + 2][2 * row] = pack2(f.z, f.z);
            *(ull*)&xs2[v + 3][2 * row] = pack2(f.w, f.w);
        }
        #pragma unroll
        for (int i = 0; i < 2; i++) {
            int idx = tid + i * 256;
            int row = idx >> 5;
            int vc = (idx & 31) * 4;
            float4 f = *(const float4*)(g_Wx + (size_t)(k0 + row) * HG + n0 + vc);
            int pb = ((vc & 4) >> 1) * 32 + (vc >> 3) * 2;
            *(ull*)&ws2[row][pb]      = pack2(f.x, f.y);
            *(ull*)&ws2[row][pb + 32] = pack2(f.z, f.w);
        }
        __syncthreads();

        #pragma unroll
        for (int kk = 0; kk < BK; kk++) {
            ull ap[8], bp[4];
            #pragma unroll
            for (int i = 0; i < 8; i++)
                ap[i] = *(const ull*)&xs2[kk][2 * (ty * 8 + i)];
            #pragma unroll
            for (int j = 0; j < 4; j++)
                bp[j] = *(const ull*)&ws2[kk][j * 32 + tx * 2];
            #pragma unroll
            for (int i = 0; i < 8; i++)
                #pragma unroll
                for (int j = 0; j < 4; j++)
                    ffma2(acc2[i][j], ap[i], bp[j]);
        }
        __syncthreads();
    }

    #pragma unroll
    for (int i = 0; i < 8; i++) {
        int m = m0 + ty * 8 + i;   // m = b*T + t
        int b = m >> 9;
        int t = m & 511;
        size_t rowbase = ((size_t)t * BB + b) * HG;
        float accf[8];
        #pragma unroll
        for (int j = 0; j < 4; j++)
            unpack2(accf[2 * j], accf[2 * j + 1], acc2[i][j]);
        #pragma unroll
        for (int j = 0; j < 8; j++) {
            int c = n0 + tx * 8 + j;
            int g = c >> 10;
            int n = c & 1023;
            g_xact[rowbase + pcol(n) + g] = accf[j] + g_bias[c];
        }
    }
}

// ---------------- software grid barrier ----------------
__device__ __forceinline__ void grid_sync_all()
{
    __threadfence();
    __syncthreads();
    if (threadIdx.x == 0) {
        unsigned gen = atomicAdd(&g_bar_gen, 0u);
        unsigned arrived = atomicAdd(&g_bar_count, 1u);
        if (arrived == gridDim.x - 1) {
            g_bar_count = 0;
            __threadfence();
            atomicExch(&g_bar_gen, gen + 1u);
        } else {
            while (atomicAdd(&g_bar_gen, 0u) == gen) { __nanosleep(32); }
        }
        __threadfence();
    }
    __syncthreads();
}

// ---------------- persistent recurrence kernel v3 ----------------
// 128 CTAs x 256 threads. CTA j owns packed cols [32j, 32j+32) = 16 f32x2 pairs.
// Warp w (0..7) = k-slice (within each 128-k chunk, rows 16w..16w+15).
// Lane = (mi,ni): mi=0..15 -> batches 4mi..4mi+3 ; ni=0..1 -> pairs 8ni..8ni+7.
// Per kk: 1 contiguous LDS.128 (activations, conflict-free) + 4 broadcast
// LDS.128 (weights) + 32 FFMA2. Cross-warp 8-way k-split reduced via smem.
#define PCTAS 128
#define CHK 128                  // k-chunk
#define NCH (HH / CHK)           // 8
#define RSTRIDE 34               // redux: 34 ull per thread (16B-aligned, padded)

__global__ __launch_bounds__(256, 1)
void lstm_persist_kernel(float* __restrict__ out)
{
    extern __shared__ float smem[];
    float* ws = smem;                         // [1024][32] floats = 128 KB (Wh slice)
    float* hs = smem + 32 * HH;               // [128][64] floats  =  32 KB (h chunk)
    ull* redux = (ull*)(smem + 32 * HH);      // 256 x 34 ull = 68 KB (aliases hs; used after)

    const int j = blockIdx.x;
    const int tid = threadIdx.x;
    const int w = tid >> 5;                   // warp = k-slice
    const int lane = tid & 31;
    const int mi = lane >> 1;                 // 0..15 batch-quad
    const int ni = lane & 1;                  // 0..1  pair-group

    // ---- load this CTA's Wh slice into smem (once): straight 128 KB copy ----
    {
        const float4* src = (const float4*)(g_Whp);
        float4* dst = (float4*)ws;
        for (int i = tid; i < HH * 8; i += 256) {
            int k = i >> 3;
            int cc = i & 7;
            dst[k * 8 + cc] = src[(size_t)k * (HG / 4) + j * 8 + cc];
        }
    }
    __syncthreads();

    // pointwise ownership (fixed across steps): b = tid>>2, n = 8j + 2q, 2q+1
    const int pb = tid >> 2;
    const int pq = tid & 3;
    float c0 = 0.0f, c1 = 0.0f;

    float4 pf[8];   // h-chunk prefetch (32 KB / 256 thr / 16 B = 8 float4)

    for (int t = 0; t < TT; t++) {
        const float* hcur = g_hbufT[t & 1];
        float* hnxt = g_hbufT[(t + 1) & 1];

        ull acc[4][8];
        #pragma unroll
        for (int i = 0; i < 4; i++)
            #pragma unroll
            for (int p = 0; p < 8; p++) acc[i][p] = 0ULL;

        // prefetch chunk 0 (contiguous: hbufT[k][b] flat)
        #pragma unroll
        for (int r = 0; r < 8; r++)
            pf[r] = __ldcg((const float4*)(hcur) + tid + r * 256);

        #pragma unroll 1
        for (int ch = 0; ch < NCH; ch++) {
            __syncthreads();   // hs free (prev chunk consumed / redux done)
            #pragma unroll
            for (int r = 0; r < 8; r++)
                ((float4*)hs)[tid + r * 256] = pf[r];
            if (ch < NCH - 1) {
                #pragma unroll
                for (int r = 0; r < 8; r++)
                    pf[r] = __ldcg((const float4*)(hcur + (ch + 1) * CHK * BB) + tid + r * 256);
            }
            __syncthreads();   // hs ready

            const int kbase = ch * CHK + w * 16;
            #pragma unroll 8
            for (int s = 0; s < 16; s++) {
                const int krow = kbase + s;
                const int hrow = w * 16 + s;
                // activations: 4 batches, one contiguous LDS.128 per lane
                float4 av = *(const float4*)&hs[hrow * BB + mi * 4];
                ull a0 = pack2(av.x, av.x);
                ull a1 = pack2(av.y, av.y);
                ull a2 = pack2(av.z, av.z);
                ull a3 = pack2(av.w, av.w);
                // weights: 8 pairs (64 B), 4 broadcast LDS.128
                const float* wr = &ws[krow * 32 + ni * 16];
                ulonglong2 w01 = *(const ulonglong2*)(wr + 0);
                ulonglong2 w23 = *(const ulonglong2*)(wr + 4);
                ulonglong2 w45 = *(const ulonglong2*)(wr + 8);
                ulonglong2 w67 = *(const ulonglong2*)(wr + 12);
                ffma2(acc[0][0], a0, w01.x); ffma2(acc[0][1], a0, w01.y);
                ffma2(acc[0][2], a0, w23.x); ffma2(acc[0][3], a0, w23.y);
                ffma2(acc[0][4], a0, w45.x); ffma2(acc[0][5], a0, w45.y);
                ffma2(acc[0][6], a0, w67.x); ffma2(acc[0][7], a0, w67.y);
                ffma2(acc[1][0], a1, w01.x); ffma2(acc[1][1], a1, w01.y);
                ffma2(acc[1][2], a1, w23.x); ffma2(acc[1][3], a1, w23.y);
                ffma2(acc[1][4], a1, w45.x); ffma2(acc[1][5], a1, w45.y);
                ffma2(acc[1][6], a1, w67.x); ffma2(acc[1][7], a1, w67.y);
                ffma2(acc[2][0], a2, w01.x); ffma2(acc[2][1], a2, w01.y);
                ffma2(acc[2][2], a2, w23.x); ffma2(acc[2][3], a2, w23.y);
                ffma2(acc[2][4], a2, w45.x); ffma2(acc[2][5], a2, w45.y);
                ffma2(acc[2][6], a2, w67.x); ffma2(acc[2][7], a2, w67.y);
                ffma2(acc[3][0], a3, w01.x); ffma2(acc[3][1], a3, w01.y);
                ffma2(acc[3][2], a3, w23.x); ffma2(acc[3][3], a3, w23.y);
                ffma2(acc[3][4], a3, w45.x); ffma2(acc[3][5], a3, w45.y);
                ffma2(acc[3][6], a3, w67.x); ffma2(acc[3][7], a3, w67.y);
            }
        }

        // ---- cross-warp reduction (8 k-slices) via smem ----
        __syncthreads();                     // all hs reads done; redux region free
        {
            ull* myr = redux + tid * RSTRIDE;
            #pragma unroll
            for (int i = 0; i < 4; i++)
                #pragma unroll
                for (int p = 0; p < 8; p += 2)
                    *(ulonglong2*)&myr[i * 8 + p] = make_ulonglong2(acc[i][p], acc[i][p + 1]);
        }
        __syncthreads();

        // ---- reduce + pointwise: thread owns (b=pb, n=8j+2pq, 8j+2pq+1) ----
        {
            const int owner_lane = (pb >> 2) * 2 + (pq >> 1);
            const int slot_b = (pb & 3) * 8;
            ull sum[4];      // pairs 4pq..4pq+3 = {if,go} for n, then n+1
            #pragma unroll
            for (int pp = 0; pp < 4; pp++) {
                int p = 4 * pq + pp;
                int slot = slot_b + (p & 7);
                ull s = redux[(0 * 32 + owner_lane) * RSTRIDE + slot];
                #pragma unroll
                for (int si = 1; si < 8; si++)
                    s = fadd2(s, redux[(si * 32 + owner_lane) * RSTRIDE + slot]);
                sum[pp] = s;
            }

            const float* xr = g_xact + ((size_t)t * BB + pb) * HG + j * 32 + pq * 8;
            float4 x0 = __ldcs((const float4*)xr);
            float4 x1 = __ldcs((const float4*)(xr + 4));

            float si0, sf0, sg0, so0, si1, sf1, sg1, so1;
            unpack2(si0, sf0, sum[0]); unpack2(sg0, so0, sum[1]);
            unpack2(si1, sf1, sum[2]); unpack2(sg1, so1, sum[3]);

            float i0 = 1.0f / (1.0f + expf(-(si0 + x0.x)));
            float f0 = 1.0f / (1.0f + expf(-(sf0 + x0.y)));
            float g0 = tanhf(sg0 + x0.z);
            float o0 = 1.0f / (1.0f + expf(-(so0 + x0.w)));
            float i1 = 1.0f / (1.0f + expf(-(si1 + x1.x)));
            float f1 = 1.0f / (1.0f + expf(-(sf1 + x1.y)));
            float g1 = tanhf(sg1 + x1.z);
            float o1 = 1.0f / (1.0f + expf(-(so1 + x1.w)));

            c0 = f0 * c0 + i0 * g0;
            c1 = f1 * c1 + i1 * g1;
            float h0 = o0 * tanhf(c0);
            float h1 = o1 * tanhf(c1);

            const int n0i = 8 * j + 2 * pq;
            hnxt[(n0i + 0) * BB + pb] = h0;
            hnxt[(n0i + 1) * BB + pb] = h1;
            float2 ho = make_float2(h0, h1);
            *(float2*)(out + ((size_t)pb * TT + t) * HH + n0i) = ho;
        }

        grid_sync_all();   // h(t+1) fully written before any CTA starts step t+1
    }
}

// ---------------- launch ----------------
extern "C" void kernel_launch(void* const* d_in, const int* in_sizes, int n_in,
                              void* d_out, int out_size)
{
    const float* x   = (const float*)d_in[0];
    const float* Wii = (const float*)d_in[1];
    const float* bii = (const float*)d_in[2];
    const float* Whi = (const float*)d_in[3];
    const float* bhi = (const float*)d_in[4];
    const float* Wif = (const float*)d_in[5];
    const float* bif = (const float*)d_in[6];
    const float* Whf = (const float*)d_in[7];
    const float* bhf = (const float*)d_in[8];
    const float* Wig = (const float*)d_in[9];
    const float* big = (const float*)d_in[10];
    const float* Whg = (const float*)d_in[11];
    const float* bhg = (const float*)d_in[12];
    const float* Wio = (const float*)d_in[13];
    const float* bio = (const float*)d_in[14];
    const float* Who = (const float*)d_in[15];
    const float* bho = (const float*)d_in[16];
    float* out = (float*)d_out;

    pack_kernel<<<512, 256>>>(Wii, Wif, Wig, Wio, Whi, Whf, Whg, Who,
                              bii, bif, big, bio, bhi, bhf, bhg, bho);

    // phase 1: (32768 x 4096) = X (32768 x 1024) @ Wx (1024 x 4096)
    gemm_x_kernel<<<dim3(HG / BN, (BB * TT) / BM), 256>>>(x);

    // phase 2: single persistent kernel for all 512 steps
    const int smem_bytes = 32 * HH * (int)sizeof(float) + 256 * RSTRIDE * 8; // 128KB + 68KB
    cudaFuncSetAttribute(lstm_persist_kernel,
                         cudaFuncAttributeMaxDynamicSharedMemorySize, smem_bytes);
    lstm_persist_kernel<<<PCTAS, 256, smem_bytes>>>(out);
}